// round 4
// baseline (speedup 1.0000x reference)
#include <cuda_runtime.h>

// DispCorrM: out[b,d,h,w] = (1/C) * sum_c L[b,c,h,w] * R[b,c,h,w-d]   (0 if w<d)
// Fixed shapes: B=4, C=32, H=256, W=512, D=64.
//
// R4: NW=8 register tile (TW=256) cuts LDS traffic 1.5 -> 1.0 B/FMA.
// Even/odd 16B-granule de-interleaving keeps every mainloop LDS.128 at
// 16B lane stride (conflict-free) despite the 32B-per-lane logical stride.

#define BB 4
#define CC 32
#define HH 256
#define WW 512
#define DD 64

#define TW 256           // w-tile per block
#define RW 320           // R tile width incl. 64-col left halo
#define ND 16            // d's per thread (per warp)
#define NW 8             // w's per thread
#define CH 8             // channels per chunk (4 chunks, double-buffered)

typedef float4 f4;

__device__ __forceinline__ void cp_async16(unsigned smem_addr, const void* gptr) {
    asm volatile("cp.async.cg.shared.global [%0], [%1], 16;\n"
                 :: "r"(smem_addr), "l"(gptr));
}
__device__ __forceinline__ void cp_commit() {
    asm volatile("cp.async.commit_group;\n");
}
template <int N>
__device__ __forceinline__ void cp_wait() {
    asm volatile("cp.async.wait_group %0;\n" :: "n"(N));
}

__global__ __launch_bounds__(128)
void disp_corr_kernel(const float* __restrict__ x, float* __restrict__ out) {
    // Even/odd granule split: XE[g] holds 16B-granule 2g, XO[g] holds 2g+1.
    __shared__ f4 LE[2][CH][TW / 8];   // 2 x 4 KB
    __shared__ f4 LO[2][CH][TW / 8];   // 2 x 4 KB
    __shared__ f4 RE[2][CH][RW / 8];   // 2 x 5 KB
    __shared__ f4 RO[2][CH][RW / 8];   // 2 x 5 KB  -> 36 KB total

    const int tile = blockIdx.x;            // 0..1
    const int h    = blockIdx.y;            // 0..255
    const int b    = blockIdx.z;            // 0..3
    const int tile_start = tile * TW;
    const int tid = threadIdx.x;

    const size_t HW = (size_t)HH * WW;

    const float* Lg = x + ((size_t)(b * 2 * CC) * HH + h) * WW + tile_start;
    const float* Rg = x + ((size_t)(b * 2 * CC + CC) * HH + h) * WW;

    // ---- async chunk loader: channels [ck*CH, ck*CH+CH) -> buffer buf ----
    auto load_chunk = [&](int ck, int buf) {
        const int c0 = ck * CH;
        // L: CH * TW/4 = 512 granules, 4 per thread
        #pragma unroll
        for (int k = 0; k < 4; k++) {
            int idx = k * 128 + tid;
            int c  = idx >> 6;          // granules per channel row = 64
            int gi = idx & 63;
            f4* dst = (gi & 1) ? &LO[buf][c][gi >> 1] : &LE[buf][c][gi >> 1];
            cp_async16((unsigned)__cvta_generic_to_shared(dst),
                       Lg + (size_t)(c0 + c) * HW + gi * 4);
        }
        // R: CH * RW/4 = 640 granules, 5 per thread
        #pragma unroll
        for (int k = 0; k < 5; k++) {
            int idx = k * 128 + tid;
            int c  = idx / 80;          // granules per channel row = 80
            int gi = idx % 80;
            f4* dst = (gi & 1) ? &RO[buf][c][gi >> 1] : &RE[buf][c][gi >> 1];
            int wg = tile_start + gi * 4 - 64;
            if (wg >= 0) {
                cp_async16((unsigned)__cvta_generic_to_shared(dst),
                           Rg + (size_t)(c0 + c) * HW + wg);
            } else {
                *dst = make_float4(0.f, 0.f, 0.f, 0.f);
            }
        }
        cp_commit();
    };

    const int lane = tid & 31;
    const int warp = tid >> 5;            // 0..3
    const int w0 = lane * 8;              // 8 w's per thread, 32 lanes cover TW=256
    const int d0 = warp * ND;             // 0,16,32,48

    // R window base: float index rlo = 64 + w0 - d0 - 16 = 48 + 8*lane - 16*warp.
    // Granule index G0 = rlo/4 = 12 + 2*lane - 4*warp  (always even).
    // gb = G0/2: window granules = RE[gb],RO[gb],RE[gb+1],RO[gb+1],RE[gb+2],RO[gb+2].
    const int gb = 6 + lane - 2 * warp;   // 0..37, gb+2 <= 39 < RW/8

    float acc[ND][NW];
    #pragma unroll
    for (int i = 0; i < ND; i++)
        #pragma unroll
        for (int j = 0; j < NW; j++) acc[i][j] = 0.f;

    auto compute_chunk = [&](int buf) {
        #pragma unroll 2
        for (int c = 0; c < CH; c++) {
            f4 La = LE[buf][c][lane];     // w0..w0+3   (16B lane stride: conflict-free)
            f4 Lb = LO[buf][c][lane];     // w0+4..w0+7
            float Lf[NW] = {La.x, La.y, La.z, La.w, Lb.x, Lb.y, Lb.z, Lb.w};

            float r[24];
            *(f4*)&r[0]  = RE[buf][c][gb];
            *(f4*)&r[4]  = RO[buf][c][gb];
            *(f4*)&r[8]  = RE[buf][c][gb + 1];
            *(f4*)&r[12] = RO[buf][c][gb + 1];
            *(f4*)&r[16] = RE[buf][c][gb + 2];
            *(f4*)&r[20] = RO[buf][c][gb + 2];

            // acc[dd][i] += L[w0+i] * R[w0+i-d0-dd]; r[k] = R(rlo+k), k = 16-dd+i
            #pragma unroll
            for (int dd = 0; dd < ND; dd++)
                #pragma unroll
                for (int i = 0; i < NW; i++)
                    acc[dd][i] = fmaf(Lf[i], r[16 - dd + i], acc[dd][i]);
        }
    };

    // ---- pipeline: 4 chunks, 2 buffers ----
    load_chunk(0, 0);            // group 0
    load_chunk(1, 1);            // group 1
    cp_wait<1>();  __syncthreads();
    compute_chunk(0);
    __syncthreads();
    load_chunk(2, 0);            // group 2
    cp_wait<1>();  __syncthreads();
    compute_chunk(1);
    __syncthreads();
    load_chunk(3, 1);            // group 3
    cp_wait<1>();  __syncthreads();
    compute_chunk(0);
    cp_wait<0>();  __syncthreads();
    compute_chunk(1);

    // ---- Epilogue: scale by 1/C and store ----
    const float inv_c = 1.0f / (float)CC;
    float* og = out + (((size_t)b * DD + d0) * HH + h) * WW + tile_start + w0;
    #pragma unroll
    for (int dd = 0; dd < ND; dd++) {
        f4 v0 = make_float4(acc[dd][0] * inv_c, acc[dd][1] * inv_c,
                            acc[dd][2] * inv_c, acc[dd][3] * inv_c);
        f4 v1 = make_float4(acc[dd][4] * inv_c, acc[dd][5] * inv_c,
                            acc[dd][6] * inv_c, acc[dd][7] * inv_c);
        *(f4*)(og + (size_t)dd * HW)     = v0;
        *(f4*)(og + (size_t)dd * HW + 4) = v1;
    }
}

extern "C" void kernel_launch(void* const* d_in, const int* in_sizes, int n_in,
                              void* d_out, int out_size) {
    const float* x = (const float*)d_in[0];
    float* out = (float*)d_out;
    dim3 grid(WW / TW, HH, BB);   // (2, 256, 4) = 2048 blocks
    disp_corr_kernel<<<grid, 128>>>(x, out);
}

// round 5
// speedup vs baseline: 1.4745x; 1.4745x over previous
#include <cuda_runtime.h>

// DispCorrM: out[b,d,h,w] = (1/C) * sum_c L[b,c,h,w] * R[b,c,h,w-d]   (0 if w<d)
// x: (B, 2C, H, W) fp32, L = x[:, :C], R = x[:, C:]
// Fixed shapes: B=4, C=32, H=256, W=512, D=64.
//
// R5: R3's proven tile (NW=4, ND=16, TW=128, cp.async double-buffer) with a
// zero-overhead mainloop: full channel unroll + base-pointer immediate-offset
// LDS addressing, occupancy pinned at 5 CTAs/SM.

#define BB 4
#define CC 32
#define HH 256
#define WW 512
#define DD 64

#define TW 128           // w-tile per block
#define RW (64 + TW)     // R tile width incl. 64-col left halo/zero-pad
#define ND 16            // d's per thread (per warp)
#define NW 4             // w's per thread
#define CH 16            // channels per chunk (2 chunks, double-buffered)

typedef float4 f4;

__device__ __forceinline__ void cp_async16(unsigned smem_addr, const void* gptr) {
    asm volatile("cp.async.cg.shared.global [%0], [%1], 16;\n"
                 :: "r"(smem_addr), "l"(gptr));
}
__device__ __forceinline__ void cp_commit() {
    asm volatile("cp.async.commit_group;\n");
}
template <int N>
__device__ __forceinline__ void cp_wait() {
    asm volatile("cp.async.wait_group %0;\n" :: "n"(N));
}

__global__ __launch_bounds__(128, 5)
void disp_corr_kernel(const float* __restrict__ x, float* __restrict__ out) {
    __shared__ float Lsh[2][CH][TW];   // 2 x 8 KB
    __shared__ float Rsh[2][CH][RW];   // 2 x 12 KB

    const int tile = blockIdx.x;            // 0..3
    const int h    = blockIdx.y;            // 0..255
    const int b    = blockIdx.z;            // 0..3
    const int tile_start = tile * TW;
    const int tid = threadIdx.x;

    const size_t HW = (size_t)HH * WW;

    const float* Lg = x + ((size_t)(b * 2 * CC) * HH + h) * WW + tile_start;
    const float* Rg = x + ((size_t)(b * 2 * CC + CC) * HH + h) * WW;

    // ---- async chunk loader: channels [ck*CH, ck*CH+CH) -> buffer ck ----
    auto load_chunk = [&](int ck) {
        const int c0 = ck * CH;
        // L: CH*TW/4 = 512 float4, 4 per thread
        #pragma unroll
        for (int k = 0; k < (CH * TW / 4) / 128; k++) {
            int idx = k * 128 + tid;
            int c  = idx / (TW / 4);
            int w4 = idx % (TW / 4);
            unsigned sa = (unsigned)__cvta_generic_to_shared(&Lsh[ck][c][4 * w4]);
            cp_async16(sa, Lg + (size_t)(c0 + c) * HW + 4 * w4);
        }
        // R: CH*RW/4 = 768 float4, 6 per thread
        #pragma unroll
        for (int k = 0; k < (CH * (RW / 4)) / 128; k++) {
            int idx = k * 128 + tid;
            int c  = idx / (RW / 4);
            int j4 = idx % (RW / 4);
            int wg = tile_start + 4 * j4 - 64;
            if (wg >= 0) {
                unsigned sa = (unsigned)__cvta_generic_to_shared(&Rsh[ck][c][4 * j4]);
                cp_async16(sa, Rg + (size_t)(c0 + c) * HW + wg);
            } else {
                *(f4*)&Rsh[ck][c][4 * j4] = make_float4(0.f, 0.f, 0.f, 0.f);
            }
        }
        cp_commit();
    };

    load_chunk(0);   // group 0 in flight

    const int lane = tid & 31;
    const int warp = tid >> 5;            // 0..3
    const int w0 = lane * 4;              // stride-16B across lanes: conflict-free LDS.128
    const int d0 = warp * ND;             // 0,16,32,48

    float acc[ND][NW];
    #pragma unroll
    for (int i = 0; i < ND; i++)
        #pragma unroll
        for (int j = 0; j < NW; j++) acc[i][j] = 0.f;

    // R shared index for (w0+i, d0+dd) is 64 + w0 + i - d0 - dd = rbase + 16 - dd + i
    const int rbase = 64 + w0 - d0 - 16;   // multiple of 4

    // Base pointers (runtime lane/warp part folded in once); all per-channel
    // offsets below are compile-time immediates in the LDS encoding.
    auto compute_chunk = [&](int ck) {
        const f4* lp = (const f4*)&Lsh[ck][0][w0];      // + c*(TW/4)
        const f4* rp = (const f4*)&Rsh[ck][0][rbase];   // + c*(RW/4) + q

        #pragma unroll
        for (int c = 0; c < CH; c++) {
            f4 Lv = lp[c * (TW / 4)];

            float r[20];
            #pragma unroll
            for (int q = 0; q < 5; q++)
                *(f4*)&r[4 * q] = rp[c * (RW / 4) + q];

            #pragma unroll
            for (int dd = 0; dd < ND; dd++) {
                acc[dd][0] = fmaf(Lv.x, r[16 - dd + 0], acc[dd][0]);
                acc[dd][1] = fmaf(Lv.y, r[16 - dd + 1], acc[dd][1]);
                acc[dd][2] = fmaf(Lv.z, r[16 - dd + 2], acc[dd][2]);
                acc[dd][3] = fmaf(Lv.w, r[16 - dd + 3], acc[dd][3]);
            }
        }
    };

    // Pipeline: start chunk 1 loads, then compute chunk 0 (hides DRAM latency), then chunk 1.
    load_chunk(1);   // group 1 in flight
    cp_wait<1>();    // chunk 0 landed
    __syncthreads();
    compute_chunk(0);
    cp_wait<0>();    // chunk 1 landed
    __syncthreads();
    compute_chunk(1);

    // ---- Epilogue: scale by 1/C and store (float4, contiguous per warp) ----
    const float inv_c = 1.0f / (float)CC;
    float* og = out + (((size_t)b * DD + d0) * HH + h) * WW + tile_start + w0;
    #pragma unroll
    for (int dd = 0; dd < ND; dd++) {
        f4 v = make_float4(acc[dd][0] * inv_c, acc[dd][1] * inv_c,
                           acc[dd][2] * inv_c, acc[dd][3] * inv_c);
        *(f4*)(og + (size_t)dd * HW) = v;
    }
}

extern "C" void kernel_launch(void* const* d_in, const int* in_sizes, int n_in,
                              void* d_out, int out_size) {
    const float* x = (const float*)d_in[0];
    float* out = (float*)d_out;
    dim3 grid(WW / TW, HH, BB);   // (4, 256, 4) = 4096 blocks
    disp_corr_kernel<<<grid, 128>>>(x, out);
}